// round 14
// baseline (speedup 1.0000x reference)
#include <cuda_runtime.h>
#include <math.h>

// ---------------------------------------------------------------------------
// Fully-fused persistent kernel: 4 lean grid barriers + final arrive-join.
// R12 skeleton with BLK=1024 (single-variable change: more warps/SM to hide
// the dependent global-latency chains that dominate the runtime).
//
// loss = sum_i event_i*(log(denom_i) - xbeta0_i) + n*lv0
//      + clip(exp(-lv1),0,1) * cost2 + lv1
// order   = stable descending sort by time (ties: lower original index first)
// denom_i = cumsum(exp(xbeta0[order]))[i]
// cost2   = M(M+1)/2 - sum_ii exp(-xh_ii) * cumsum(exp(xh))[ii]
//
// Sort: time uniform in [0,1000) -> 2^18 value buckets in DESCENDING time
// order; counting sort + per-bucket insertion sort on 50-bit composite key.
// Each block owns CH=2048 consecutive buckets; elements contiguous in
// g_keys => segment sorted in SMEM. Pass A caches (xbeta,event) in SMEM.
//
// GRID<=148 x 1024, all co-resident => spin barrier safe (1 spinner/CTA).
// Zero-at-entry invariants: g_hist (re-zeroed in scatter), g_blkTot
// (g_blkTot[b] re-zeroed by block b in scatter), g_fin (block 0 resets).
// ---------------------------------------------------------------------------

#define MAXN (1 << 19)
#define NB   (1 << 18)
#define MAXM 16384
#define BLK  1024
#define NW   (BLK / 32)         // 32 warps
#define CH   2048
#define EPT_B (CH / BLK)        // 2 buckets per thread
#define MAXG 148
#define SEGCAP 2816             // 2048 + 17 sigma; global fallback beyond

__device__ unsigned long long g_keys[MAXN];
__device__ int    g_hist[NB];
__device__ int    g_off_mut[NB];
__device__ int    g_blkTot[MAXG];    // zero at entry; [b] re-zeroed in scatter
__device__ double g_coxBlk[MAXG];
__device__ double g_blockAcc[MAXG];
__device__ float  g_xh[MAXM];
__device__ unsigned g_bar_gen = 0;   // monotone across replays (ok)
__device__ unsigned g_bar_cnt = 0;   // returns to 0 after each barrier
__device__ unsigned g_fin     = 0;   // final join; block 0 resets

__device__ __forceinline__ unsigned ld_acquire(const unsigned* p) {
    unsigned v;
    asm volatile("ld.acquire.gpu.b32 %0, [%1];" : "=r"(v) : "l"(p) : "memory");
    return v;
}

__device__ __forceinline__ void grid_bar(int G) {
    __syncthreads();
    if (threadIdx.x == 0) {
        unsigned gen = ld_acquire(&g_bar_gen);
        __threadfence();
        unsigned arrived = atomicAdd(&g_bar_cnt, 1u);
        if (arrived == (unsigned)(G - 1)) {
            g_bar_cnt = 0;
            __threadfence();
            atomicAdd(&g_bar_gen, 1u);
        } else {
            while (ld_acquire(&g_bar_gen) == gen) { }
        }
        __threadfence();
    }
    __syncthreads();
}

// ---- shuffle block primitives (BLK = 1024 = 32 warps) ----
__device__ __forceinline__ int block_reduce_i(int v, volatile int* shw, int t) {
    int lane = t & 31;
#pragma unroll
    for (int o = 16; o > 0; o >>= 1) v += __shfl_down_sync(0xffffffffu, v, o);
    if (lane == 0) shw[t >> 5] = v;
    __syncthreads();
    if (t < NW) {
        int x = shw[t];
#pragma unroll
        for (int o = NW / 2; o > 0; o >>= 1) x += __shfl_down_sync(0xffffffffu, x, o);
        if (t == 0) shw[0] = x;
    }
    __syncthreads();
    int r = shw[0];
    __syncthreads();
    return r;
}

__device__ __forceinline__ double block_reduce_d(double v, volatile double* shw, int t) {
    int lane = t & 31;
#pragma unroll
    for (int o = 16; o > 0; o >>= 1) v += __shfl_down_sync(0xffffffffu, v, o);
    if (lane == 0) shw[t >> 5] = v;
    __syncthreads();
    if (t < NW) {
        double x = shw[t];
#pragma unroll
        for (int o = NW / 2; o > 0; o >>= 1) x += __shfl_down_sync(0xffffffffu, x, o);
        if (t == 0) shw[0] = x;
    }
    __syncthreads();
    double r = shw[0];
    __syncthreads();
    return r;
}

__device__ __forceinline__ int block_scan_excl_i(int v, volatile int* shw, int t) {
    int lane = t & 31, w = t >> 5;
    int x = v;
#pragma unroll
    for (int o = 1; o < 32; o <<= 1) {
        int u = __shfl_up_sync(0xffffffffu, x, o);
        if (lane >= o) x += u;
    }
    if (lane == 31) shw[w] = x;
    __syncthreads();
    if (t < NW) {
        int y = shw[t];
#pragma unroll
        for (int o = 1; o < NW; o <<= 1) {
            int u = __shfl_up_sync(0xffffffffu, y, o);
            if (t >= o) y += u;
        }
        shw[t] = y;
    }
    __syncthreads();
    int r = ((w == 0) ? 0 : shw[w - 1]) + x - v;
    __syncthreads();
    return r;
}

__device__ __forceinline__ double block_scan_excl_d(double v, volatile double* shw, int t) {
    int lane = t & 31, w = t >> 5;
    double x = v;
#pragma unroll
    for (int o = 1; o < 32; o <<= 1) {
        double u = __shfl_up_sync(0xffffffffu, x, o);
        if (lane >= o) x += u;
    }
    if (lane == 31) shw[w] = x;
    __syncthreads();
    if (t < NW) {
        double y = shw[t];
#pragma unroll
        for (int o = 1; o < NW; o <<= 1) {
            double u = __shfl_up_sync(0xffffffffu, y, o);
            if (t >= o) y += u;
        }
        shw[t] = y;
    }
    __syncthreads();
    double r = ((w == 0) ? 0.0 : shw[w - 1]) + x - v;
    __syncthreads();
    return r;
}

__device__ __forceinline__ int bucket_desc(float t) {
    int b = (int)(t * ((float)NB / 1000.0f));
    if (b < 0) b = 0;
    if (b > NB - 1) b = NB - 1;
    return (NB - 1) - b;
}

__global__ __launch_bounds__(BLK, 1)
void fused_kernel(const float* __restrict__ yt0, const float* __restrict__ yp0,
                  const float* __restrict__ yp1, const int* __restrict__ Hj,
                  const float* __restrict__ lv, float* __restrict__ out,
                  int n, int m, int idx_bits, unsigned idx_mask, int G) {
    __shared__ unsigned long long s_keys[SEGCAP];   // 22528 B
    __shared__ float2 s_xe[SEGCAP];                 // 22528 B (xbeta, event)
    __shared__ int    s_dest[MAXG];                 // per-destination counts
    __shared__ int    shw_i[NW];
    __shared__ double shw_d[NW];

    const int b = blockIdx.x, t = threadIdx.x;
    const long baseN = (long)b * CH;
    const long endN  = (baseN + CH < n) ? baseN + CH : n;
    const long baseB = (long)b * CH;
    const long endB  = (baseB + CH < NB) ? baseB + CH : NB;
    const float2* yt2 = (const float2*)yt0;

    // ---- P1: histogram + per-destination-block counts ----
    if (t < MAXG) s_dest[t] = 0;
    __syncthreads();
    for (long i = baseN + t; i < endN; i += BLK) {
        int bu = bucket_desc(yt2[i].x);
        atomicAdd(&g_hist[bu], 1);
        atomicAdd_block(&s_dest[bu / CH], 1);
    }
    __syncthreads();
    if (t < G) {
        int c = s_dest[t];
        if (c > 0) atomicAdd(&g_blkTot[t], c);
    }
    grid_bar(G);   // bar 1 (hist + blkTot final)

    // ---- P2: counts (regs), segment start, bucket offsets ----
    const long myB0 = baseB + (long)t * EPT_B;
    int cnt[EPT_B];
    int cntSum = 0;
#pragma unroll
    for (int k = 0; k < EPT_B; k++) {
        long bu = myB0 + k;
        cnt[k] = (bu < endB) ? g_hist[bu] : 0;
        cntSum += cnt[k];
    }
    const int ownTot = g_blkTot[b];                   // final after bar1
    int bv = (t < b) ? g_blkTot[t] : 0;               // G <= BLK
    const int segStart = block_reduce_i(bv, shw_i, t);
    const int pref_i = block_scan_excl_i(cntSum, shw_i, t);
    int off0[EPT_B];
    {
        int run = segStart + pref_i;
#pragma unroll
        for (int k = 0; k < EPT_B; k++) {
            off0[k] = run;
            long bu = myB0 + k;
            if (bu < endB) g_off_mut[bu] = run;
            run += cnt[k];
        }
    }
    grid_bar(G);   // bar 2 (offsets visible before scatter)

    // ---- P3: scatter keys; re-zero hist chunk + own blkTot ----
    for (long i = baseN + t; i < endN; i += BLK) {
        float2 te = yt2[i];
        unsigned u = __float_as_uint(te.x);
        u = (u & 0x80000000u) ? ~u : (u | 0x80000000u);
        unsigned long long key = ((unsigned long long)u << idx_bits) |
                                 (unsigned long long)(idx_mask - (unsigned)i);
        int bu = bucket_desc(te.x);
        int pos = atomicAdd(&g_off_mut[bu], 1);
        g_keys[pos] = key;
    }
    for (long i = baseB + t; i < endB; i += BLK) g_hist[i] = 0;
    if (t == 0) g_blkTot[b] = 0;
    grid_bar(G);   // bar 3 (all keys placed before segment reads)

    // ---- P4: smem segment sort; Hj serve; pass A (gather+exp+cache) ----
    const int seg = ownTot;
    const bool useSmem = (seg <= SEGCAP);
    unsigned long long* kb;              // indexed by GLOBAL element index
    if (useSmem) {
        for (int i = t; i < seg; i += BLK) s_keys[i] = g_keys[segStart + i];
        kb = s_keys - segStart;
    } else {
        kb = g_keys;
    }
    __syncthreads();

#pragma unroll
    for (int k = 0; k < EPT_B; k++) {
        int s = off0[k], e = s + cnt[k];
        for (int i = s + 1; i < e; i++) {
            unsigned long long kk = kb[i];
            int j = i - 1;
            while (j >= s && kb[j] < kk) { kb[j + 1] = kb[j]; j--; }
            kb[j + 1] = kk;
        }
    }
    __syncthreads();

    // serve ordinal ranks landing in my segment (high-MLP sweep)
    {
        int HPT = (m + BLK - 1) / BLK;
        int segEnd2 = segStart + seg;
        for (int k2 = 0; k2 < HPT; k2++) {
            int j = t * HPT + k2;
            if (j < m) {
                int r = Hj[j];
                if (r >= segStart && r < segEnd2) {
                    unsigned long long kk = kb[r];
                    unsigned orig = idx_mask - (unsigned)(kk & idx_mask);
                    g_xh[j] = yp1[orig];
                }
            }
        }
    }

    // pass A: gather (xbeta, event), exp-sum, cache into smem
    double exSum = 0.0;
    {
        int s = off0[0];
        for (int i2 = 0; i2 < cntSum; i2++) {
            unsigned long long kk = kb[s + i2];
            unsigned orig = idx_mask - (unsigned)(kk & idx_mask);
            float xbv = yp0[orig];
            float evv = yt2[orig].y;
            exSum += (double)expf(xbv);
            if (useSmem) s_xe[s - segStart + i2] = make_float2(xbv, evv);
        }
    }
    const double pref_d = block_scan_excl_d(exSum, shw_d, t);
    {
        double tot = block_reduce_d(exSum, shw_d, t);
        if (t == 0) g_coxBlk[b] = tot;
    }
    grid_bar(G);   // bar 4

    // ---- P5: Cox prefix + loss (smem-only pass B) ----
    {
        double bv2 = (t < b) ? g_coxBlk[t] : 0.0;
        double base_val = block_reduce_d(bv2, shw_d, t);
        double run = base_val + pref_d;
        double acc = 0.0;
        int s = off0[0];
        if (useSmem) {
            int loc = s - segStart;
            for (int i2 = 0; i2 < cntSum; i2++) {
                float2 xe = s_xe[loc + i2];
                run += (double)expf(xe.x);
                if (xe.y != 0.0f)
                    acc += (double)logf((float)run) - (double)xe.x;
            }
        } else {
            for (int i2 = 0; i2 < cntSum; i2++) {
                unsigned long long kk = kb[s + i2];
                unsigned orig = idx_mask - (unsigned)(kk & idx_mask);
                float xbv = yp0[orig];
                float evv = yt2[orig].y;
                run += (double)expf(xbv);
                if (evv != 0.0f)
                    acc += (double)logf((float)run) - (double)xbv;
            }
        }
        double tot = block_reduce_d(acc, shw_d, t);
        if (t == 0) {
            g_blockAcc[b] = tot;
            __threadfence();
            atomicAdd(&g_fin, 1u);
        }
    }

    // ---- P6: only block 0 continues: wait-all, ordinal scan, combine ----
    if (b != 0) return;
    if (t == 0) {
        while (ld_acquire(&g_fin) < (unsigned)G) { }
        g_fin = 0;
        __threadfence();
    }
    __syncthreads();

    {
        int S = (m + BLK - 1) / BLK;
        double tot = 0.0;
        for (int k2 = 0; k2 < S; k2++) {
            int j = t * S + k2;
            if (j < m) tot += (double)expf(__ldcg(&g_xh[j]));
        }
        double pref2 = block_scan_excl_d(tot, shw_d, t);
        double run2 = pref2;
        double acc2 = 0.0;
        for (int k2 = 0; k2 < S; k2++) {
            int j = t * S + k2;
            if (j < m) {
                float x = __ldcg(&g_xh[j]);
                run2 += (double)expf(x);
                acc2 += run2 * (double)expf(-x);
            }
        }
        double sAcc = block_reduce_d(acc2, shw_d, t);
        double cost2 = 0.5 * (double)m * ((double)m + 1.0) - sAcc;

        double s2 = 0.0;
        for (int k2 = t; k2 < G; k2 += BLK) s2 += __ldcg(&g_blockAcc[k2]);
        double coxTot = block_reduce_d(s2, shw_d, t);

        if (t == 0) {
            double lv0 = (double)lv[0];
            double lv1 = (double)lv[1];
            double p1 = exp(-lv1);
            if (p1 > 1.0) p1 = 1.0;
            if (p1 < 0.0) p1 = 0.0;
            out[0] = (float)((coxTot + (double)n * lv0) + (p1 * cost2 + lv1));
        }
    }
}

extern "C" void kernel_launch(void* const* d_in, const int* in_sizes, int n_in,
                              void* d_out, int out_size) {
    const float* yt0      = (const float*)d_in[0];   // [N,2] (time, event)
    const float* yp0      = (const float*)d_in[2];   // [N,1] xbeta head 0
    const float* yp1      = (const float*)d_in[3];   // [N,1] xbeta head 1
    const int*   Hj       = (const int*)d_in[4];     // [M]
    const float* log_vars = (const float*)d_in[5];   // [2]

    int n = in_sizes[0] / 2;
    int m = in_sizes[4];

    int idx_bits = 0;
    while ((1u << idx_bits) < (unsigned)n) idx_bits++;
    unsigned idx_mask = (1u << idx_bits) - 1u;

    int G  = (n + CH - 1) / CH;               // 128 for N=262144
    int GB = (NB + CH - 1) / CH;              // 128
    if (GB > G) G = GB;
    if (G > MAXG) G = MAXG;

    fused_kernel<<<G, BLK>>>(yt0, yp0, yp1, Hj, log_vars, (float*)d_out,
                             n, m, idx_bits, idx_mask, G);
}

// round 16
// speedup vs baseline: 1.1590x; 1.1590x over previous
#include <cuda_runtime.h>
#include <math.h>

// ---------------------------------------------------------------------------
// Fully-fused persistent kernel: 4 lean grid barriers + final arrive-join.
// R12 skeleton; scatter carries (key, payload) as 16B structs so the
// post-sort Cox passes are SMEM-only (no random gathers).
//
// loss = sum_i event_i*(log(denom_i) - xbeta0_i) + n*lv0
//      + clip(exp(-lv1),0,1) * cost2 + lv1
// order   = stable descending sort by time (ties: lower original index first)
// denom_i = cumsum(exp(xbeta0[order]))[i]
// cost2   = M(M+1)/2 - sum_ii exp(-xh_ii) * cumsum(exp(xh))[ii]
//
// Sort: time uniform in [0,1000) -> 2^18 value buckets in DESCENDING time
// order; counting sort + per-bucket insertion sort on 50-bit composite key.
// Each block owns CH=2048 consecutive buckets; elements contiguous in
// g_kv => segment sorted in SMEM as ulonglong2 {key, (event,xbeta0)}.
//
// GRID<=148 x 512, all co-resident => spin barrier safe (1 spinner/CTA).
// Zero-at-entry invariants: g_hist (re-zeroed in scatter), g_blkTot
// (g_blkTot[b] re-zeroed by block b in scatter), g_fin (block 0 resets).
// ---------------------------------------------------------------------------

#define MAXN (1 << 19)
#define NB   (1 << 18)
#define MAXM 16384
#define BLK  512
#define NW   (BLK / 32)
#define CH   2048
#define EPT_B (CH / BLK)        // 4 buckets per thread
#define MAXG 148
#define SEGCAP 2816             // 2048 + 17 sigma; global fallback beyond

__device__ ulonglong2 g_kv[MAXN];    // {key, payload}; payload = ev<<32 | xb
__device__ int    g_hist[NB];
__device__ int    g_off_mut[NB];
__device__ int    g_blkTot[MAXG];    // zero at entry; [b] re-zeroed in scatter
__device__ double g_coxBlk[MAXG];
__device__ double g_blockAcc[MAXG];
__device__ float  g_xh[MAXM];
__device__ unsigned g_bar_gen = 0;   // monotone across replays (ok)
__device__ unsigned g_bar_cnt = 0;   // returns to 0 after each barrier
__device__ unsigned g_fin     = 0;   // final join; block 0 resets

__device__ __forceinline__ unsigned ld_acquire(const unsigned* p) {
    unsigned v;
    asm volatile("ld.acquire.gpu.b32 %0, [%1];" : "=r"(v) : "l"(p) : "memory");
    return v;
}

__device__ __forceinline__ void grid_bar(int G) {
    __syncthreads();
    if (threadIdx.x == 0) {
        unsigned gen = ld_acquire(&g_bar_gen);
        __threadfence();
        unsigned arrived = atomicAdd(&g_bar_cnt, 1u);
        if (arrived == (unsigned)(G - 1)) {
            g_bar_cnt = 0;
            __threadfence();
            atomicAdd(&g_bar_gen, 1u);
        } else {
            while (ld_acquire(&g_bar_gen) == gen) { }
        }
        __threadfence();
    }
    __syncthreads();
}

// ---- shuffle block primitives (BLK = 512 = 16 warps) ----
__device__ __forceinline__ int block_reduce_i(int v, volatile int* shw, int t) {
    int lane = t & 31;
#pragma unroll
    for (int o = 16; o > 0; o >>= 1) v += __shfl_down_sync(0xffffffffu, v, o);
    if (lane == 0) shw[t >> 5] = v;
    __syncthreads();
    if (t < NW) {
        int x = shw[t];
#pragma unroll
        for (int o = NW / 2; o > 0; o >>= 1) x += __shfl_down_sync((1u << NW) - 1u, x, o);
        if (t == 0) shw[0] = x;
    }
    __syncthreads();
    int r = shw[0];
    __syncthreads();
    return r;
}

__device__ __forceinline__ double block_reduce_d(double v, volatile double* shw, int t) {
    int lane = t & 31;
#pragma unroll
    for (int o = 16; o > 0; o >>= 1) v += __shfl_down_sync(0xffffffffu, v, o);
    if (lane == 0) shw[t >> 5] = v;
    __syncthreads();
    if (t < NW) {
        double x = shw[t];
#pragma unroll
        for (int o = NW / 2; o > 0; o >>= 1) x += __shfl_down_sync((1u << NW) - 1u, x, o);
        if (t == 0) shw[0] = x;
    }
    __syncthreads();
    double r = shw[0];
    __syncthreads();
    return r;
}

__device__ __forceinline__ int block_scan_excl_i(int v, volatile int* shw, int t) {
    int lane = t & 31, w = t >> 5;
    int x = v;
#pragma unroll
    for (int o = 1; o < 32; o <<= 1) {
        int u = __shfl_up_sync(0xffffffffu, x, o);
        if (lane >= o) x += u;
    }
    if (lane == 31) shw[w] = x;
    __syncthreads();
    if (t < NW) {
        int y = shw[t];
#pragma unroll
        for (int o = 1; o < NW; o <<= 1) {
            int u = __shfl_up_sync((1u << NW) - 1u, y, o);
            if (t >= o) y += u;
        }
        shw[t] = y;
    }
    __syncthreads();
    int r = ((w == 0) ? 0 : shw[w - 1]) + x - v;
    __syncthreads();
    return r;
}

__device__ __forceinline__ double block_scan_excl_d(double v, volatile double* shw, int t) {
    int lane = t & 31, w = t >> 5;
    double x = v;
#pragma unroll
    for (int o = 1; o < 32; o <<= 1) {
        double u = __shfl_up_sync(0xffffffffu, x, o);
        if (lane >= o) x += u;
    }
    if (lane == 31) shw[w] = x;
    __syncthreads();
    if (t < NW) {
        double y = shw[t];
#pragma unroll
        for (int o = 1; o < NW; o <<= 1) {
            double u = __shfl_up_sync((1u << NW) - 1u, y, o);
            if (t >= o) y += u;
        }
        shw[t] = y;
    }
    __syncthreads();
    double r = ((w == 0) ? 0.0 : shw[w - 1]) + x - v;
    __syncthreads();
    return r;
}

__device__ __forceinline__ int bucket_desc(float t) {
    int b = (int)(t * ((float)NB / 1000.0f));
    if (b < 0) b = 0;
    if (b > NB - 1) b = NB - 1;
    return (NB - 1) - b;
}

__global__ __launch_bounds__(BLK, 1)
void fused_kernel(const float* __restrict__ yt0, const float* __restrict__ yp0,
                  const float* __restrict__ yp1, const int* __restrict__ Hj,
                  const float* __restrict__ lv, float* __restrict__ out,
                  int n, int m, int idx_bits, unsigned idx_mask, int G) {
    __shared__ ulonglong2 s_kv[SEGCAP];   // 45056 B {key, payload}
    __shared__ int    s_dest[MAXG];
    __shared__ int    shw_i[NW];
    __shared__ double shw_d[NW];

    const int b = blockIdx.x, t = threadIdx.x;
    const long baseN = (long)b * CH;
    const long endN  = (baseN + CH < n) ? baseN + CH : n;
    const long baseB = (long)b * CH;
    const long endB  = (baseB + CH < NB) ? baseB + CH : NB;
    const float2* yt2 = (const float2*)yt0;

    // ---- P1: histogram + per-destination-block counts ----
    if (t < MAXG) s_dest[t] = 0;
    __syncthreads();
    for (long i = baseN + t; i < endN; i += BLK) {
        int bu = bucket_desc(yt2[i].x);
        atomicAdd(&g_hist[bu], 1);
        atomicAdd_block(&s_dest[bu / CH], 1);
    }
    __syncthreads();
    if (t < G) {
        int c = s_dest[t];
        if (c > 0) atomicAdd(&g_blkTot[t], c);
    }
    grid_bar(G);   // bar 1 (hist + blkTot final)

    // ---- P2: counts (regs), segment start, bucket offsets ----
    const long myB0 = baseB + (long)t * EPT_B;
    int cnt[EPT_B];
    int cntSum = 0;
#pragma unroll
    for (int k = 0; k < EPT_B; k++) {
        long bu = myB0 + k;
        cnt[k] = (bu < endB) ? g_hist[bu] : 0;
        cntSum += cnt[k];
    }
    const int ownTot = g_blkTot[b];                   // final after bar1
    int bv = (t < b) ? g_blkTot[t] : 0;               // G <= BLK
    const int segStart = block_reduce_i(bv, shw_i, t);
    const int pref_i = block_scan_excl_i(cntSum, shw_i, t);
    int off0[EPT_B];
    {
        int run = segStart + pref_i;
#pragma unroll
        for (int k = 0; k < EPT_B; k++) {
            off0[k] = run;
            long bu = myB0 + k;
            if (bu < endB) g_off_mut[bu] = run;
            run += cnt[k];
        }
    }
    grid_bar(G);   // bar 2 (offsets visible before scatter)

    // ---- P3: scatter (key,payload); re-zero hist chunk + own blkTot ----
    for (long i = baseN + t; i < endN; i += BLK) {
        float2 te = yt2[i];
        float xbv = yp0[i];                           // coalesced
        unsigned u = __float_as_uint(te.x);
        u = (u & 0x80000000u) ? ~u : (u | 0x80000000u);
        unsigned long long key = ((unsigned long long)u << idx_bits) |
                                 (unsigned long long)(idx_mask - (unsigned)i);
        unsigned long long pay = ((unsigned long long)__float_as_uint(te.y) << 32) |
                                 (unsigned long long)__float_as_uint(xbv);
        int bu = bucket_desc(te.x);
        int pos = atomicAdd(&g_off_mut[bu], 1);
        g_kv[pos] = make_ulonglong2(key, pay);        // one STG.128
    }
    for (long i = baseB + t; i < endB; i += BLK) g_hist[i] = 0;
    if (t == 0) g_blkTot[b] = 0;
    grid_bar(G);   // bar 3 (all structs placed before segment reads)

    // ---- P4: smem segment sort (16B structs); Hj serve; pass A ----
    const int seg = ownTot;
    const bool useSmem = (seg <= SEGCAP);
    ulonglong2* kb;                      // indexed by GLOBAL element index
    if (useSmem) {
        for (int i = t; i < seg; i += BLK) s_kv[i] = g_kv[segStart + i];
        kb = s_kv - segStart;
    } else {
        kb = g_kv;
    }
    __syncthreads();

    // per-bucket insertion sort (descending key); payload moves with key
#pragma unroll
    for (int k = 0; k < EPT_B; k++) {
        int s = off0[k], e = s + cnt[k];
        for (int i = s + 1; i < e; i++) {
            ulonglong2 kk = kb[i];
            int j = i - 1;
            while (j >= s && kb[j].x < kk.x) { kb[j + 1] = kb[j]; j--; }
            kb[j + 1] = kk;
        }
    }
    __syncthreads();

    // serve ordinal ranks landing in my segment (high-MLP sweep over Hj)
    {
        int HPT = (m + BLK - 1) / BLK;
        int segEnd2 = segStart + seg;
        for (int k2 = 0; k2 < HPT; k2++) {
            int j = t * HPT + k2;
            if (j < m) {
                int r = Hj[j];
                if (r >= segStart && r < segEnd2) {
                    unsigned long long kk = kb[r].x;
                    unsigned orig = idx_mask - (unsigned)(kk & idx_mask);
                    g_xh[j] = yp1[orig];
                }
            }
        }
    }

    // pass A: exp-sum over own buckets' elements (SMEM payload only)
    double exSum = 0.0;
    {
        int s = off0[0];
        for (int i2 = 0; i2 < cntSum; i2++) {
            float xbv = __uint_as_float((unsigned)kb[s + i2].y);
            exSum += (double)expf(xbv);
        }
    }
    const double pref_d = block_scan_excl_d(exSum, shw_d, t);
    {
        double tot = block_reduce_d(exSum, shw_d, t);
        if (t == 0) g_coxBlk[b] = tot;
    }
    grid_bar(G);   // bar 4

    // ---- P5: Cox prefix + loss (SMEM payload only) ----
    {
        double bv2 = (t < b) ? g_coxBlk[t] : 0.0;
        double base_val = block_reduce_d(bv2, shw_d, t);
        double run = base_val + pref_d;
        double acc = 0.0;
        int s = off0[0];
        for (int i2 = 0; i2 < cntSum; i2++) {
            unsigned long long pay = kb[s + i2].y;
            float xbv = __uint_as_float((unsigned)pay);
            float evv = __uint_as_float((unsigned)(pay >> 32));
            run += (double)expf(xbv);
            if (evv != 0.0f)
                acc += (double)logf((float)run) - (double)xbv;
        }
        double tot = block_reduce_d(acc, shw_d, t);
        if (t == 0) {
            g_blockAcc[b] = tot;
            __threadfence();
            atomicAdd(&g_fin, 1u);
        }
    }

    // ---- P6: only block 0 continues: wait-all, ordinal scan, combine ----
    if (b != 0) return;
    if (t == 0) {
        while (ld_acquire(&g_fin) < (unsigned)G) { }
        g_fin = 0;
        __threadfence();
    }
    __syncthreads();

    {
        int S = (m + BLK - 1) / BLK;
        double tot = 0.0;
        for (int k2 = 0; k2 < S; k2++) {
            int j = t * S + k2;
            if (j < m) tot += (double)expf(__ldcg(&g_xh[j]));
        }
        double pref2 = block_scan_excl_d(tot, shw_d, t);
        double run2 = pref2;
        double acc2 = 0.0;
        for (int k2 = 0; k2 < S; k2++) {
            int j = t * S + k2;
            if (j < m) {
                float x = __ldcg(&g_xh[j]);
                run2 += (double)expf(x);
                acc2 += run2 * (double)expf(-x);
            }
        }
        double sAcc = block_reduce_d(acc2, shw_d, t);
        double cost2 = 0.5 * (double)m * ((double)m + 1.0) - sAcc;

        double s2 = 0.0;
        for (int k2 = t; k2 < G; k2 += BLK) s2 += __ldcg(&g_blockAcc[k2]);
        double coxTot = block_reduce_d(s2, shw_d, t);

        if (t == 0) {
            double lv0 = (double)lv[0];
            double lv1 = (double)lv[1];
            double p1 = exp(-lv1);
            if (p1 > 1.0) p1 = 1.0;
            if (p1 < 0.0) p1 = 0.0;
            out[0] = (float)((coxTot + (double)n * lv0) + (p1 * cost2 + lv1));
        }
    }
}

extern "C" void kernel_launch(void* const* d_in, const int* in_sizes, int n_in,
                              void* d_out, int out_size) {
    const float* yt0      = (const float*)d_in[0];   // [N,2] (time, event)
    const float* yp0      = (const float*)d_in[2];   // [N,1] xbeta head 0
    const float* yp1      = (const float*)d_in[3];   // [N,1] xbeta head 1
    const int*   Hj       = (const int*)d_in[4];     // [M]
    const float* log_vars = (const float*)d_in[5];   // [2]

    int n = in_sizes[0] / 2;
    int m = in_sizes[4];

    int idx_bits = 0;
    while ((1u << idx_bits) < (unsigned)n) idx_bits++;
    unsigned idx_mask = (1u << idx_bits) - 1u;

    int G  = (n + CH - 1) / CH;               // 128 for N=262144
    int GB = (NB + CH - 1) / CH;              // 128
    if (GB > G) G = GB;
    if (G > MAXG) G = MAXG;

    fused_kernel<<<G, BLK>>>(yt0, yp0, yp1, Hj, log_vars, (float*)d_out,
                             n, m, idx_bits, idx_mask, G);
}

// round 17
// speedup vs baseline: 1.3089x; 1.1293x over previous
#include <cuda_runtime.h>
#include <math.h>

// ---------------------------------------------------------------------------
// Fully-fused persistent kernel: 4 lean grid barriers + final arrive-join.
// R14 skeleton + (a) uniform element-chunked Cox passes (payload in SMEM,
// no Poisson straggler), (b) ordinal scan overlapped with other blocks' P5.
//
// loss = sum_i event_i*(log(denom_i) - xbeta0_i) + n*lv0
//      + clip(exp(-lv1),0,1) * cost2 + lv1
// order   = stable descending sort by time (ties: lower original index first)
// denom_i = cumsum(exp(xbeta0[order]))[i]
// cost2   = M(M+1)/2 - sum_ii exp(-xh_ii) * cumsum(exp(xh))[ii]
//
// Sort: time uniform in [0,1000) -> 2^18 value buckets in DESCENDING time
// order; counting sort + per-bucket insertion sort on 50-bit composite key.
// Each block owns CH=2048 consecutive buckets; elements contiguous in
// g_kv => segment sorted in SMEM as ulonglong2 {key, (event,xbeta0)}.
//
// GRID<=148 x 512, all co-resident => spin barrier safe (1 spinner/CTA).
// Zero-at-entry invariants: g_hist (re-zeroed in scatter), g_blkTot
// (g_blkTot[b] re-zeroed by block b in scatter), g_fin (block 0 resets).
// ---------------------------------------------------------------------------

#define MAXN (1 << 19)
#define NB   (1 << 18)
#define MAXM 16384
#define BLK  512
#define NW   (BLK / 32)
#define CH   2048
#define EPT_B (CH / BLK)        // 4 buckets per thread
#define MAXG 148
#define SEGCAP 2816             // 2048 + 17 sigma; global fallback beyond

__device__ ulonglong2 g_kv[MAXN];    // {key, payload}; payload = ev<<32 | xb
__device__ int    g_hist[NB];
__device__ int    g_off_mut[NB];
__device__ int    g_blkTot[MAXG];    // zero at entry; [b] re-zeroed in scatter
__device__ double g_coxBlk[MAXG];
__device__ double g_blockAcc[MAXG];
__device__ float  g_xh[MAXM];
__device__ unsigned g_bar_gen = 0;   // monotone across replays (ok)
__device__ unsigned g_bar_cnt = 0;   // returns to 0 after each barrier
__device__ unsigned g_fin     = 0;   // final join; block 0 resets

__device__ __forceinline__ unsigned ld_acquire(const unsigned* p) {
    unsigned v;
    asm volatile("ld.acquire.gpu.b32 %0, [%1];" : "=r"(v) : "l"(p) : "memory");
    return v;
}

__device__ __forceinline__ void grid_bar(int G) {
    __syncthreads();
    if (threadIdx.x == 0) {
        unsigned gen = ld_acquire(&g_bar_gen);
        __threadfence();
        unsigned arrived = atomicAdd(&g_bar_cnt, 1u);
        if (arrived == (unsigned)(G - 1)) {
            g_bar_cnt = 0;
            __threadfence();
            atomicAdd(&g_bar_gen, 1u);
        } else {
            while (ld_acquire(&g_bar_gen) == gen) { }
        }
        __threadfence();
    }
    __syncthreads();
}

// ---- shuffle block primitives (BLK = 512 = 16 warps) ----
__device__ __forceinline__ int block_reduce_i(int v, volatile int* shw, int t) {
    int lane = t & 31;
#pragma unroll
    for (int o = 16; o > 0; o >>= 1) v += __shfl_down_sync(0xffffffffu, v, o);
    if (lane == 0) shw[t >> 5] = v;
    __syncthreads();
    if (t < NW) {
        int x = shw[t];
#pragma unroll
        for (int o = NW / 2; o > 0; o >>= 1) x += __shfl_down_sync((1u << NW) - 1u, x, o);
        if (t == 0) shw[0] = x;
    }
    __syncthreads();
    int r = shw[0];
    __syncthreads();
    return r;
}

__device__ __forceinline__ double block_reduce_d(double v, volatile double* shw, int t) {
    int lane = t & 31;
#pragma unroll
    for (int o = 16; o > 0; o >>= 1) v += __shfl_down_sync(0xffffffffu, v, o);
    if (lane == 0) shw[t >> 5] = v;
    __syncthreads();
    if (t < NW) {
        double x = shw[t];
#pragma unroll
        for (int o = NW / 2; o > 0; o >>= 1) x += __shfl_down_sync((1u << NW) - 1u, x, o);
        if (t == 0) shw[0] = x;
    }
    __syncthreads();
    double r = shw[0];
    __syncthreads();
    return r;
}

__device__ __forceinline__ int block_scan_excl_i(int v, volatile int* shw, int t) {
    int lane = t & 31, w = t >> 5;
    int x = v;
#pragma unroll
    for (int o = 1; o < 32; o <<= 1) {
        int u = __shfl_up_sync(0xffffffffu, x, o);
        if (lane >= o) x += u;
    }
    if (lane == 31) shw[w] = x;
    __syncthreads();
    if (t < NW) {
        int y = shw[t];
#pragma unroll
        for (int o = 1; o < NW; o <<= 1) {
            int u = __shfl_up_sync((1u << NW) - 1u, y, o);
            if (t >= o) y += u;
        }
        shw[t] = y;
    }
    __syncthreads();
    int r = ((w == 0) ? 0 : shw[w - 1]) + x - v;
    __syncthreads();
    return r;
}

__device__ __forceinline__ double block_scan_excl_d(double v, volatile double* shw, int t) {
    int lane = t & 31, w = t >> 5;
    double x = v;
#pragma unroll
    for (int o = 1; o < 32; o <<= 1) {
        double u = __shfl_up_sync(0xffffffffu, x, o);
        if (lane >= o) x += u;
    }
    if (lane == 31) shw[w] = x;
    __syncthreads();
    if (t < NW) {
        double y = shw[t];
#pragma unroll
        for (int o = 1; o < NW; o <<= 1) {
            double u = __shfl_up_sync((1u << NW) - 1u, y, o);
            if (t >= o) y += u;
        }
        shw[t] = y;
    }
    __syncthreads();
    double r = ((w == 0) ? 0.0 : shw[w - 1]) + x - v;
    __syncthreads();
    return r;
}

__device__ __forceinline__ int bucket_desc(float t) {
    int b = (int)(t * ((float)NB / 1000.0f));
    if (b < 0) b = 0;
    if (b > NB - 1) b = NB - 1;
    return (NB - 1) - b;
}

__global__ __launch_bounds__(BLK, 1)
void fused_kernel(const float* __restrict__ yt0, const float* __restrict__ yp0,
                  const float* __restrict__ yp1, const int* __restrict__ Hj,
                  const float* __restrict__ lv, float* __restrict__ out,
                  int n, int m, int idx_bits, unsigned idx_mask, int G) {
    __shared__ ulonglong2 s_kv[SEGCAP];   // 45056 B {key, payload}
    __shared__ int    s_dest[MAXG];
    __shared__ int    shw_i[NW];
    __shared__ double shw_d[NW];
    __shared__ double s_cost2;

    const int b = blockIdx.x, t = threadIdx.x;
    const long baseN = (long)b * CH;
    const long endN  = (baseN + CH < n) ? baseN + CH : n;
    const long baseB = (long)b * CH;
    const long endB  = (baseB + CH < NB) ? baseB + CH : NB;
    const float2* yt2 = (const float2*)yt0;

    // ---- P1: histogram + per-destination-block counts ----
    if (t < MAXG) s_dest[t] = 0;
    __syncthreads();
    for (long i = baseN + t; i < endN; i += BLK) {
        int bu = bucket_desc(yt2[i].x);
        atomicAdd(&g_hist[bu], 1);
        atomicAdd_block(&s_dest[bu / CH], 1);
    }
    __syncthreads();
    if (t < G) {
        int c = s_dest[t];
        if (c > 0) atomicAdd(&g_blkTot[t], c);
    }
    grid_bar(G);   // bar 1 (hist + blkTot final)

    // ---- P2: counts (regs), segment start, bucket offsets ----
    const long myB0 = baseB + (long)t * EPT_B;
    int cnt[EPT_B];
    int cntSum = 0;
#pragma unroll
    for (int k = 0; k < EPT_B; k++) {
        long bu = myB0 + k;
        cnt[k] = (bu < endB) ? g_hist[bu] : 0;
        cntSum += cnt[k];
    }
    const int ownTot = g_blkTot[b];                   // final after bar1
    int bv = (t < b) ? g_blkTot[t] : 0;               // G <= BLK
    const int segStart = block_reduce_i(bv, shw_i, t);
    const int pref_i = block_scan_excl_i(cntSum, shw_i, t);
    int off0[EPT_B];
    {
        int run = segStart + pref_i;
#pragma unroll
        for (int k = 0; k < EPT_B; k++) {
            off0[k] = run;
            long bu = myB0 + k;
            if (bu < endB) g_off_mut[bu] = run;
            run += cnt[k];
        }
    }
    grid_bar(G);   // bar 2 (offsets visible before scatter)

    // ---- P3: scatter (key,payload); re-zero hist chunk + own blkTot ----
    for (long i = baseN + t; i < endN; i += BLK) {
        float2 te = yt2[i];
        float xbv = yp0[i];                           // coalesced
        unsigned u = __float_as_uint(te.x);
        u = (u & 0x80000000u) ? ~u : (u | 0x80000000u);
        unsigned long long key = ((unsigned long long)u << idx_bits) |
                                 (unsigned long long)(idx_mask - (unsigned)i);
        unsigned long long pay = ((unsigned long long)__float_as_uint(te.y) << 32) |
                                 (unsigned long long)__float_as_uint(xbv);
        int bu = bucket_desc(te.x);
        int pos = atomicAdd(&g_off_mut[bu], 1);
        g_kv[pos] = make_ulonglong2(key, pay);        // one STG.128
    }
    for (long i = baseB + t; i < endB; i += BLK) g_hist[i] = 0;
    if (t == 0) g_blkTot[b] = 0;
    grid_bar(G);   // bar 3 (all structs placed before segment reads)

    // ---- P4: smem segment sort (16B structs); Hj serve; pass A ----
    const int seg = ownTot;
    const bool useSmem = (seg <= SEGCAP);
    ulonglong2* kb;                      // indexed by GLOBAL element index
    if (useSmem) {
        for (int i = t; i < seg; i += BLK) s_kv[i] = g_kv[segStart + i];
        kb = s_kv - segStart;
    } else {
        kb = g_kv;
    }
    __syncthreads();

    // per-bucket insertion sort (descending key); payload moves with key
#pragma unroll
    for (int k = 0; k < EPT_B; k++) {
        int s = off0[k], e = s + cnt[k];
        for (int i = s + 1; i < e; i++) {
            ulonglong2 kk = kb[i];
            int j = i - 1;
            while (j >= s && kb[j].x < kk.x) { kb[j + 1] = kb[j]; j--; }
            kb[j + 1] = kk;
        }
    }
    __syncthreads();

    // serve ordinal ranks landing in my segment (high-MLP sweep over Hj)
    {
        int HPT = (m + BLK - 1) / BLK;
        int segEnd2 = segStart + seg;
        for (int k2 = 0; k2 < HPT; k2++) {
            int j = t * HPT + k2;
            if (j < m) {
                int r = Hj[j];
                if (r >= segStart && r < segEnd2) {
                    unsigned long long kk = kb[r].x;
                    unsigned orig = idx_mask - (unsigned)(kk & idx_mask);
                    g_xh[j] = yp1[orig];
                }
            }
        }
    }

    // pass A: UNIFORM element chunks over the sorted segment (SMEM payload)
    const int E = (seg + BLK - 1) / BLK;
    const int myLo = t * E;
    const int myHi = (myLo + E < seg) ? myLo + E : seg;
    double exSum = 0.0;
    for (int i2 = myLo; i2 < myHi; i2++) {
        float xbv = __uint_as_float((unsigned)kb[segStart + i2].y);
        exSum += (double)expf(xbv);
    }
    const double pref_d = block_scan_excl_d(exSum, shw_d, t);
    {
        double tot = block_reduce_d(exSum, shw_d, t);
        if (t == 0) g_coxBlk[b] = tot;
    }
    grid_bar(G);   // bar 4 (g_xh + g_coxBlk final)

    // ---- P5a (block 0 only): ordinal scan, overlapped with others' P5 ----
    if (b == 0) {
        int S = (m + BLK - 1) / BLK;
        double tot = 0.0;
        for (int k2 = 0; k2 < S; k2++) {
            int j = t * S + k2;
            if (j < m) tot += (double)expf(__ldcg(&g_xh[j]));
        }
        double pref2 = block_scan_excl_d(tot, shw_d, t);
        double run2 = pref2;
        double acc2 = 0.0;
        for (int k2 = 0; k2 < S; k2++) {
            int j = t * S + k2;
            if (j < m) {
                float x = __ldcg(&g_xh[j]);
                run2 += (double)expf(x);
                acc2 += run2 * (double)expf(-x);
            }
        }
        double sAcc = block_reduce_d(acc2, shw_d, t);
        if (t == 0)
            s_cost2 = 0.5 * (double)m * ((double)m + 1.0) - sAcc;
        __syncthreads();
    }

    // ---- P5: Cox prefix + loss (uniform chunks, SMEM payload) ----
    {
        double bv2 = (t < b) ? g_coxBlk[t] : 0.0;     // final since bar4
        double base_val = block_reduce_d(bv2, shw_d, t);
        double run = base_val + pref_d;
        double acc = 0.0;
        for (int i2 = myLo; i2 < myHi; i2++) {
            unsigned long long pay = kb[segStart + i2].y;
            float xbv = __uint_as_float((unsigned)pay);
            float evv = __uint_as_float((unsigned)(pay >> 32));
            run += (double)expf(xbv);
            if (evv != 0.0f)
                acc += (double)logf((float)run) - (double)xbv;
        }
        double tot = block_reduce_d(acc, shw_d, t);
        if (t == 0) {
            g_blockAcc[b] = tot;
            if (b != 0) {
                __threadfence();
                atomicAdd(&g_fin, 1u);
            }
        }
    }

    // ---- P6: only block 0: wait for others' blockAcc, combine ----
    if (b != 0) return;
    if (t == 0) {
        while (ld_acquire(&g_fin) < (unsigned)(G - 1)) { }
        g_fin = 0;
        __threadfence();
    }
    __syncthreads();

    {
        double s2 = 0.0;
        for (int k2 = t; k2 < G; k2 += BLK) s2 += __ldcg(&g_blockAcc[k2]);
        double coxTot = block_reduce_d(s2, shw_d, t);

        if (t == 0) {
            double lv0 = (double)lv[0];
            double lv1 = (double)lv[1];
            double p1 = exp(-lv1);
            if (p1 > 1.0) p1 = 1.0;
            if (p1 < 0.0) p1 = 0.0;
            out[0] = (float)((coxTot + (double)n * lv0) + (p1 * s_cost2 + lv1));
        }
    }
}

extern "C" void kernel_launch(void* const* d_in, const int* in_sizes, int n_in,
                              void* d_out, int out_size) {
    const float* yt0      = (const float*)d_in[0];   // [N,2] (time, event)
    const float* yp0      = (const float*)d_in[2];   // [N,1] xbeta head 0
    const float* yp1      = (const float*)d_in[3];   // [N,1] xbeta head 1
    const int*   Hj       = (const int*)d_in[4];     // [M]
    const float* log_vars = (const float*)d_in[5];   // [2]

    int n = in_sizes[0] / 2;
    int m = in_sizes[4];

    int idx_bits = 0;
    while ((1u << idx_bits) < (unsigned)n) idx_bits++;
    unsigned idx_mask = (1u << idx_bits) - 1u;

    int G  = (n + CH - 1) / CH;               // 128 for N=262144
    int GB = (NB + CH - 1) / CH;              // 128
    if (GB > G) G = GB;
    if (G > MAXG) G = MAXG;

    fused_kernel<<<G, BLK>>>(yt0, yp0, yp1, Hj, log_vars, (float*)d_out,
                             n, m, idx_bits, idx_mask, G);
}